// round 10
// baseline (speedup 1.0000x reference)
#include <cuda_runtime.h>
#include <cuda_bf16.h>
#include <cstdint>

#define NN 50000
#define EE 800000
#define HID 128

// Scratch (device globals — no allocation allowed)
__device__ float g_h[(size_t)NN * HID];
__device__ float g_aggr[(size_t)NN * HID];
__device__ float g_P[(size_t)NN * HID];   // h @ W1a (tgt part)
__device__ float g_Q[(size_t)NN * HID];   // h @ W1b (src part)
__device__ float g_rdeg[NN];
__device__ int g_ei_is64;
// packed split-bf16 operands
__device__ unsigned gEAh[(size_t)EE * 8];
__device__ unsigned gEAl[(size_t)EE * 8];
__device__ unsigned gW2h[2 * 128 * 64];
__device__ unsigned gW2l[2 * 128 * 64];
__device__ unsigned gW1h[2 * 128 * 8];
__device__ unsigned gW1l[2 * 128 * 8];

typedef unsigned long long u64;

#define FMA2(d, a, b) asm("fma.rn.f32x2 %0, %1, %2, %0;" : "+l"(d) : "l"(a), "l"(b))
#define PACK2(d, lo, hi) asm("mov.b64 %0, {%1, %2};" : "=l"(d) : "f"(lo), "f"(hi))
#define UNPACK2(lo, hi, s) asm("mov.b64 {%0, %1}, %2;" : "=f"(lo), "=f"(hi) : "l"(s))

#define RED2(ptr, a, b) \
    asm volatile("red.global.add.v2.f32 [%0], {%1, %2};" \
                 :: "l"(ptr), "f"(a), "f"(b) : "memory")

#define MMA16816(cc, aa, bb) \
    asm volatile("mma.sync.aligned.m16n8k16.row.col.f32.bf16.bf16.f32 " \
                 "{%0,%1,%2,%3}, {%4,%5,%6,%7}, {%8,%9}, {%0,%1,%2,%3};" \
                 : "+f"(cc[0]), "+f"(cc[1]), "+f"(cc[2]), "+f"(cc[3]) \
                 : "r"(aa[0]), "r"(aa[1]), "r"(aa[2]), "r"(aa[3]), \
                   "r"(bb[0]), "r"(bb[1]))

__device__ __forceinline__ void split2(float x, float y, unsigned& hi, unsigned& lo) {
    __nv_bfloat16 xh = __float2bfloat16_rn(x);
    __nv_bfloat16 yh = __float2bfloat16_rn(y);
    __nv_bfloat16 xl = __float2bfloat16_rn(x - __bfloat162float(xh));
    __nv_bfloat16 yl = __float2bfloat16_rn(y - __bfloat162float(yh));
    hi = ((unsigned)__bfloat16_as_ushort(yh) << 16) | __bfloat16_as_ushort(xh);
    lo = ((unsigned)__bfloat16_as_ushort(yl) << 16) | __bfloat16_as_ushort(xl);
}

__device__ __forceinline__ int permp(int p) { return 2 * (p & 3) + (p >> 2); }

// ---------------------------------------------------------------------------
__global__ void detect_ei_kernel(const unsigned* __restrict__ raw) {
    if (threadIdx.x == 0 && blockIdx.x == 0) {
        int is64 = 1;
        for (int i = 0; i < 64; i++)
            if (raw[2 * i + 1] != 0u) { is64 = 0; break; }
        g_ei_is64 = is64;
    }
}
__device__ __forceinline__ int load_ei(const void* ei, size_t idx, int is64) {
    int v = is64 ? (int)((const long long*)ei)[idx] : ((const int*)ei)[idx];
    return min(max(v, 0), NN - 1);
}

// ---------------------------------------------------------------------------
// Precompute: packed split-bf16 edge attrs (fragment layout, no xor)
// thread = (e, kq): reads float4, writes 2 slots to gEAh/gEAl
// ---------------------------------------------------------------------------
__global__ void pack_ea_kernel(const float* __restrict__ ea) {
    int tid = blockIdx.x * 256 + threadIdx.x;
    int e = tid >> 2, kq = tid & 3;
    if (e >= EE) return;
    float4 v = *(const float4*)(ea + (size_t)e * 16 + 4 * kq);
    unsigned h0, l0, h1, l1;
    split2(v.x, v.y, h0, l0);
    split2(v.z, v.w, h1, l1);
    int q0 = permp(2 * kq), q1 = permp(2 * kq + 1);
    gEAh[(size_t)e * 8 + q0] = h0; gEAl[(size_t)e * 8 + q0] = l0;
    gEAh[(size_t)e * 8 + q1] = h1; gEAl[(size_t)e * 8 + q1] = l1;
}

// ---------------------------------------------------------------------------
// Precompute: packed W2 (xor-swizzled smem image) + W1c (no xor)
// ---------------------------------------------------------------------------
__global__ void pack_w_kernel(const float* __restrict__ msg_W1,
                              const float* __restrict__ msg_W2) {
    int tid = blockIdx.x * 256 + threadIdx.x;
    if (tid < 16384) {  // W2: 2 layers x 128 n x 64 kpairs
        int l = tid >> 13, r = tid & 8191;
        int n = r >> 6, p = r & 63;
        const float* W2 = msg_W2 + (size_t)l * 128 * 128;
        float w0 = W2[(size_t)(2 * p) * 128 + n];
        float w1 = W2[(size_t)(2 * p + 1) * 128 + n];
        unsigned hi, lo;
        split2(w0, w1, hi, lo);
        int c = p >> 3, pl = p & 7;
        int slot = permp(pl) ^ (2 * (n & 3));
        gW2h[l * 8192 + n * 64 + c * 8 + slot] = hi;
        gW2l[l * 8192 + n * 64 + c * 8 + slot] = lo;
    } else if (tid < 16384 + 2048) {  // W1c: 2 layers x 128 n x 8 kpairs
        int r = tid - 16384;
        int l = r >> 10; r &= 1023;
        int n = r >> 3, p = r & 7;
        const float* W1c = msg_W1 + (size_t)l * 272 * 128 + (size_t)256 * 128;
        float w0 = W1c[(size_t)(2 * p) * 128 + n];
        float w1 = W1c[(size_t)(2 * p + 1) * 128 + n];
        unsigned hi, lo;
        split2(w0, w1, hi, lo);
        gW1h[l * 1024 + n * 8 + permp(p)] = hi;
        gW1l[l * 1024 + n * 8 + permp(p)] = lo;
    }
}

// ---------------------------------------------------------------------------
// Encoder
// ---------------------------------------------------------------------------
__global__ void enc_kernel(const float* __restrict__ x, const float* __restrict__ W,
                           const float* __restrict__ b, const float* __restrict__ g,
                           const float* __restrict__ beta) {
    int node = blockIdx.x;
    int t = threadIdx.x;
    __shared__ float sx[32];
    __shared__ float red[8];
    if (t < 32) sx[t] = x[node * 32 + t];
    __syncthreads();
    float acc = b[t];
#pragma unroll
    for (int k = 0; k < 32; k++) acc = fmaf(sx[k], W[k * HID + t], acc);
    acc = fmaxf(acc, 0.f);
    float s = acc, sq = acc * acc;
#pragma unroll
    for (int o = 16; o; o >>= 1) {
        s += __shfl_xor_sync(0xffffffffu, s, o);
        sq += __shfl_xor_sync(0xffffffffu, sq, o);
    }
    int w = t >> 5;
    if ((t & 31) == 0) { red[w] = s; red[4 + w] = sq; }
    __syncthreads();
    s = red[0] + red[1] + red[2] + red[3];
    sq = red[4] + red[5] + red[6] + red[7];
    float mu = s * (1.f / HID);
    float var = sq * (1.f / HID) - mu * mu;
    g_h[(size_t)node * HID + t] = (acc - mu) * rsqrtf(var + 1e-5f) * g[t] + beta[t];
}

// ---------------------------------------------------------------------------
__global__ void zero_aggr_kernel() {
    size_t i = (size_t)blockIdx.x * blockDim.x + threadIdx.x;
    if (i < (size_t)NN * HID) g_aggr[i] = 0.f;
}
__global__ void zero_deg_kernel() {
    int i = blockIdx.x * blockDim.x + threadIdx.x;
    if (i < NN) g_rdeg[i] = 0.f;
}
__global__ void deg_kernel(const void* __restrict__ ei) {
    int e = blockIdx.x * blockDim.x + threadIdx.x;
    int is64 = g_ei_is64;
    if (e < EE) atomicAdd(&g_rdeg[load_ei(ei, (size_t)EE + e, is64)], 1.f);
}
__global__ void rdeg_kernel() {
    int i = blockIdx.x * blockDim.x + threadIdx.x;
    if (i < NN) g_rdeg[i] = 1.f / fmaxf(g_rdeg[i], 1.f);
}

// ---------------------------------------------------------------------------
// Node GEMM: out = g_h @ W   (K=128, no bias)
// ---------------------------------------------------------------------------
__global__ void __launch_bounds__(256)
nodemm_kernel(const float* __restrict__ W, float* __restrict__ out) {
    __shared__ __align__(16) float Ast[16 * 65];
    __shared__ __align__(16) float Bs[16 * 128];

    int tid = threadIdx.x;
    int tx = tid & 15, ty = tid >> 4;
    const int col0 = tx * 8, row0 = ty * 4;
    int n0 = blockIdx.x * 64;
    int le = tid >> 2;
    int kb = (tid & 3) * 4;
    int lnode = min(n0 + le, NN - 1);

    u64 acc[4][4];
#pragma unroll
    for (int i = 0; i < 4; i++)
#pragma unroll
        for (int j = 0; j < 4; j++) acc[i][j] = 0ull;

    for (int c = 0; c < 8; c++) {
        const float* ap = g_h + (size_t)lnode * HID + c * 16 + kb;
        float4 v = *(const float4*)ap;
        const float* wp = W + c * 16 * 128;
        float4 w0 = *(const float4*)(wp + tid * 8);
        float4 w1 = *(const float4*)(wp + tid * 8 + 4);
        __syncthreads();
        Ast[(kb + 0) * 65 + le] = v.x;
        Ast[(kb + 1) * 65 + le] = v.y;
        Ast[(kb + 2) * 65 + le] = v.z;
        Ast[(kb + 3) * 65 + le] = v.w;
        *(float4*)(Bs + tid * 8) = w0;
        *(float4*)(Bs + tid * 8 + 4) = w1;
        __syncthreads();
#pragma unroll
        for (int kk = 0; kk < 16; kk++) {
            u64 a2[4];
#pragma unroll
            for (int i = 0; i < 4; i++) {
                float a = Ast[kk * 65 + row0 + i];
                PACK2(a2[i], a, a);
            }
            ulonglong2 qq0 = *(const ulonglong2*)(Bs + kk * 128 + col0);
            ulonglong2 qq1 = *(const ulonglong2*)(Bs + kk * 128 + col0 + 4);
            u64 bp[4] = {qq0.x, qq0.y, qq1.x, qq1.y};
#pragma unroll
            for (int i = 0; i < 4; i++)
#pragma unroll
                for (int j = 0; j < 4; j++) FMA2(acc[i][j], a2[i], bp[j]);
        }
    }

#pragma unroll
    for (int i = 0; i < 4; i++) {
        int node = n0 + row0 + i;
        if (node < NN) {
            float f[8];
#pragma unroll
            for (int j = 0; j < 4; j++) UNPACK2(f[2 * j], f[2 * j + 1], acc[i][j]);
            float4 o0 = {f[0], f[1], f[2], f[3]};
            float4 o1 = {f[4], f[5], f[6], f[7]};
            *(float4*)(out + (size_t)node * HID + col0) = o0;
            *(float4*)(out + (size_t)node * HID + col0 + 4) = o1;
        }
    }
}

// ---------------------------------------------------------------------------
// Message kernel — mma.sync with precomputed packed operands:
//   GEMM1: ea @ W1c      (A-frags direct LDG from gEA; B from smem W1c image)
//   epi1:  += P[tgt]+Q[src]+b1, ReLU, split; own chunks stay in regs,
//          all chunks written to sH for the sibling warp
//   GEMM2: hidden @ W2   (full W2 image staged in smem once; no per-panel sync)
//   epi2:  +b2, RED2 scatter into g_aggr[tgt]
// 64-edge x 128-col tile; warps: wm=wid&3 (16 rows), wn=wid>>2 (64 cols).
// dynamic smem = 110080 B; __launch_bounds__(256,2)
// ---------------------------------------------------------------------------
#define MSG_SMEM 110080

__global__ void __launch_bounds__(256, 2)
msg_kernel(const void* __restrict__ ei,
           const unsigned* __restrict__ w2h, const unsigned* __restrict__ w2l,
           const unsigned* __restrict__ w1h, const unsigned* __restrict__ w1l,
           const float* __restrict__ b1, const float* __restrict__ b2) {
    extern __shared__ __align__(16) char smem[];
    unsigned* sW2h = (unsigned*)smem;                    // [128][66]
    unsigned* sW2l = (unsigned*)(smem + 33792);
    unsigned* sW1h = (unsigned*)(smem + 67584);          // [128][8]
    unsigned* sW1l = (unsigned*)(smem + 71680);
    unsigned* sHh  = (unsigned*)(smem + 75776);          // [64][66]
    unsigned* sHl  = (unsigned*)(smem + 92672);
    int* s_src = (int*)(smem + 109568);
    int* s_tgt = (int*)(smem + 109824);

    int tid = threadIdx.x;
    int lane = tid & 31, wid = tid >> 5;
    int gid = lane >> 2, tig = lane & 3;
    int wm = wid & 3, wn = wid >> 2;
    int e0 = blockIdx.x * 64;
    const int sx = (2 * tig) ^ (2 * (gid & 3));

    // ---- staging: W2 image, W1c image, indices ----
    {
        int n = tid >> 1, half = tid & 1;
        const uint2* gh = (const uint2*)w2h + n * 32 + half * 16;
        const uint2* gl = (const uint2*)w2l + n * 32 + half * 16;
        int base = n * 66 + half * 32;
#pragma unroll
        for (int i = 0; i < 16; i++) {
            *(uint2*)&sW2h[base + 2 * i] = gh[i];
            *(uint2*)&sW2l[base + 2 * i] = gl[i];
        }
        *(uint2*)&sW1h[tid * 4]     = ((const uint2*)w1h)[tid * 2];
        *(uint2*)&sW1h[tid * 4 + 2] = ((const uint2*)w1h)[tid * 2 + 1];
        *(uint2*)&sW1l[tid * 4]     = ((const uint2*)w1l)[tid * 2];
        *(uint2*)&sW1l[tid * 4 + 2] = ((const uint2*)w1l)[tid * 2 + 1];
    }
    int is64 = g_ei_is64;
    if (tid < 64) s_src[tid] = load_ei(ei, (size_t)e0 + tid, is64);
    else if (tid < 128) s_tgt[tid - 64] = load_ei(ei, (size_t)EE + e0 + (tid - 64), is64);
    __syncthreads();

    float acc[8][4];
#pragma unroll
    for (int t = 0; t < 8; t++)
#pragma unroll
        for (int j = 0; j < 4; j++) acc[t][j] = 0.f;

    // ================= GEMM1: K=16, A-frags direct from gEA =================
    {
        size_t er = (size_t)(e0 + wm * 16 + gid) * 8 + 2 * tig;
        uint2 A0h = *(const uint2*)&gEAh[er];
        uint2 A1h = *(const uint2*)&gEAh[er + 64];
        uint2 A0l = *(const uint2*)&gEAl[er];
        uint2 A1l = *(const uint2*)&gEAl[er + 64];
        unsigned ah[4] = {A0h.x, A1h.x, A0h.y, A1h.y};
        unsigned al[4] = {A0l.x, A1l.x, A0l.y, A1l.y};
#pragma unroll
        for (int t = 0; t < 8; t++) {
            int nb = (wn * 64 + t * 8 + gid) * 8 + 2 * tig;
            uint2 BH = *(uint2*)&sW1h[nb];
            uint2 BL = *(uint2*)&sW1l[nb];
            unsigned bh[2] = {BH.x, BH.y};
            unsigned bl[2] = {BL.x, BL.y};
            MMA16816(acc[t], ah, bh);
            MMA16816(acc[t], ah, bl);
            MMA16816(acc[t], al, bh);
        }
    }

    // ============ epilogue 1: +P+Q+b1, ReLU, split; regs + sH ============
    unsigned H01[8], H23[8], L01[8], L23[8];
    {
        int r0 = wm * 16 + gid;
        int n0t = s_tgt[r0], n0s = s_src[r0];
        int n1t = s_tgt[r0 + 8], n1s = s_src[r0 + 8];
        const float* P0 = g_P + (size_t)n0t * HID;
        const float* Q0 = g_Q + (size_t)n0s * HID;
        const float* P1 = g_P + (size_t)n1t * HID;
        const float* Q1 = g_Q + (size_t)n1s * HID;
#pragma unroll
        for (int t = 0; t < 8; t++) {
            int col = wn * 64 + t * 8 + tig * 2;
            float bb0 = b1[col], bb1 = b1[col + 1];
            float2 p0 = *(const float2*)(P0 + col);
            float2 q0 = *(const float2*)(Q0 + col);
            float2 p1 = *(const float2*)(P1 + col);
            float2 q1 = *(const float2*)(Q1 + col);
            float x0 = fmaxf(acc[t][0] + bb0 + p0.x + q0.x, 0.f);
            float x1 = fmaxf(acc[t][1] + bb1 + p0.y + q0.y, 0.f);
            float x2 = fmaxf(acc[t][2] + bb0 + p1.x + q1.x, 0.f);
            float x3 = fmaxf(acc[t][3] + bb1 + p1.y + q1.y, 0.f);
            split2(x0, x1, H01[t], L01[t]);
            split2(x2, x3, H23[t], L23[t]);
#pragma unroll
            for (int j = 0; j < 4; j++) acc[t][j] = 0.f;
        }
        // write all own chunks to sH (sibling reads them)
#pragma unroll
        for (int cp = 0; cp < 4; cp++) {
            int c = wn * 4 + cp;
            int b0i = r0 * 66 + c * 8 + sx;
            *(uint2*)&sHh[b0i]       = make_uint2(H01[2 * cp], H01[2 * cp + 1]);
            *(uint2*)&sHh[b0i + 528] = make_uint2(H23[2 * cp], H23[2 * cp + 1]);
            *(uint2*)&sHl[b0i]       = make_uint2(L01[2 * cp], L01[2 * cp + 1]);
            *(uint2*)&sHl[b0i + 528] = make_uint2(L23[2 * cp], L23[2 * cp + 1]);
        }
    }
    __syncthreads();

    // ================= GEMM2: K=128, W2 image resident in smem ==============
    {
        int arow = (wm * 16 + gid) * 66;
#pragma unroll
        for (int c = 0; c < 8; c++) {
            unsigned ah[4], al[4];
            if ((c >> 2) == wn) {
                int cp = c & 3;
                ah[0] = H01[2 * cp]; ah[1] = H23[2 * cp];
                ah[2] = H01[2 * cp + 1]; ah[3] = H23[2 * cp + 1];
                al[0] = L01[2 * cp]; al[1] = L23[2 * cp];
                al[2] = L01[2 * cp + 1]; al[3] = L23[2 * cp + 1];
            } else {
                int b0i = arow + c * 8 + sx;
                uint2 h0 = *(uint2*)&sHh[b0i];
                uint2 h1 = *(uint2*)&sHh[b0i + 528];
                uint2 l0 = *(uint2*)&sHl[b0i];
                uint2 l1 = *(uint2*)&sHl[b0i + 528];
                ah[0] = h0.x; ah[1] = h1.x; ah[2] = h0.y; ah[3] = h1.y;
                al[0] = l0.x; al[1] = l1.x; al[2] = l0.y; al[3] = l1.y;
            }
#pragma unroll
            for (int t = 0; t < 8; t++) {
                int nb = (wn * 64 + t * 8 + gid) * 66 + c * 8 + sx;
                uint2 BH = *(uint2*)&sW2h[nb];
                uint2 BL = *(uint2*)&sW2l[nb];
                unsigned bh[2] = {BH.x, BH.y};
                unsigned bl[2] = {BL.x, BL.y};
                MMA16816(acc[t], ah, bh);
                MMA16816(acc[t], ah, bl);
                MMA16816(acc[t], al, bh);
            }
        }
    }

    // ================= epilogue 2: +b2, scatter =================
    {
        int r0 = wm * 16 + gid;
        int n0 = s_tgt[r0], n1 = s_tgt[r0 + 8];
#pragma unroll
        for (int t = 0; t < 8; t++) {
            int col = wn * 64 + t * 8 + tig * 2;
            float bb0 = b2[col], bb1 = b2[col + 1];
            RED2(g_aggr + (size_t)n0 * HID + col, acc[t][0] + bb0, acc[t][1] + bb1);
            RED2(g_aggr + (size_t)n1 * HID + col, acc[t][2] + bb0, acc[t][3] + bb1);
        }
    }
}

// ---------------------------------------------------------------------------
// Update kernel (unchanged, known-good)
// ---------------------------------------------------------------------------
__global__ void __launch_bounds__(256)
upd_kernel(const float* __restrict__ W1, const float* __restrict__ b1,
           const float* __restrict__ W2, const float* __restrict__ b2,
           const float* __restrict__ lng, const float* __restrict__ lnb) {
    __shared__ __align__(16) float Ast[16 * 65];
    __shared__ __align__(16) float Bs[16 * 128];
    __shared__ __align__(16) float Hs[64 * 132];

    int tid = threadIdx.x;
    int tx = tid & 15, ty = tid >> 4;
    const int col0 = tx * 8, row0 = ty * 4;
    int n0 = blockIdx.x * 64;
    int le = tid >> 2;
    int kb = (tid & 3) * 4;
    int lnode = min(n0 + le, NN - 1);
    float rd = g_rdeg[lnode];

    u64 acc[4][4];
#pragma unroll
    for (int i = 0; i < 4; i++)
#pragma unroll
        for (int j = 0; j < 4; j++) acc[i][j] = 0ull;

    float b1v[8], b2v[8];
#pragma unroll
    for (int j = 0; j < 8; j++) { b1v[j] = b1[col0 + j]; b2v[j] = b2[col0 + j]; }

    for (int c = 0; c < 16; c++) {
        const float* ap = (c < 8) ? g_h + (size_t)lnode * HID + c * 16 + kb
                                  : g_aggr + (size_t)lnode * HID + (c - 8) * 16 + kb;
        float4 v = *(const float4*)ap;
        if (c >= 8) { v.x *= rd; v.y *= rd; v.z *= rd; v.w *= rd; }
        const float* wp = W1 + c * 16 * 128;
        float4 w0 = *(const float4*)(wp + tid * 8);
        float4 w1 = *(const float4*)(wp + tid * 8 + 4);
        __syncthreads();
        Ast[(kb + 0) * 65 + le] = v.x;
        Ast[(kb + 1) * 65 + le] = v.y;
        Ast[(kb + 2) * 65 + le] = v.z;
        Ast[(kb + 3) * 65 + le] = v.w;
        *(float4*)(Bs + tid * 8) = w0;
        *(float4*)(Bs + tid * 8 + 4) = w1;
        __syncthreads();
#pragma unroll
        for (int kk = 0; kk < 16; kk++) {
            u64 a2[4];
#pragma unroll
            for (int i = 0; i < 4; i++) {
                float a = Ast[kk * 65 + row0 + i];
                PACK2(a2[i], a, a);
            }
            ulonglong2 qq0 = *(const ulonglong2*)(Bs + kk * 128 + col0);
            ulonglong2 qq1 = *(const ulonglong2*)(Bs + kk * 128 + col0 + 4);
            u64 bp[4] = {qq0.x, qq0.y, qq1.x, qq1.y};
#pragma unroll
            for (int i = 0; i < 4; i++)
#pragma unroll
                for (int j = 0; j < 4; j++) FMA2(acc[i][j], a2[i], bp[j]);
        }
    }

#pragma unroll
    for (int i = 0; i < 4; i++) {
        float* hrow = Hs + (row0 + i) * 132;
#pragma unroll
        for (int j = 0; j < 4; j++) {
            float lo, hi;
            UNPACK2(lo, hi, acc[i][j]);
            hrow[col0 + 2 * j]     = fmaxf(lo + b1v[2 * j], 0.f);
            hrow[col0 + 2 * j + 1] = fmaxf(hi + b1v[2 * j + 1], 0.f);
            acc[i][j] = 0ull;
        }
    }
    __syncthreads();

    for (int c = 0; c < 8; c++) {
        const float* wp = W2 + c * 16 * 128;
        float4 w0 = *(const float4*)(wp + tid * 8);
        float4 w1 = *(const float4*)(wp + tid * 8 + 4);
        __syncthreads();
        *(float4*)(Bs + tid * 8) = w0;
        *(float4*)(Bs + tid * 8 + 4) = w1;
        __syncthreads();
#pragma unroll
        for (int kk = 0; kk < 16; kk++) {
            int k = c * 16 + kk;
            u64 a2[4];
#pragma unroll
            for (int i = 0; i < 4; i++) {
                float a = Hs[(row0 + i) * 132 + k];
                PACK2(a2[i], a, a);
            }
            ulonglong2 qq0 = *(const ulonglong2*)(Bs + kk * 128 + col0);
            ulonglong2 qq1 = *(const ulonglong2*)(Bs + kk * 128 + col0 + 4);
            u64 bp[4] = {qq0.x, qq0.y, qq1.x, qq1.y};
#pragma unroll
            for (int i = 0; i < 4; i++)
#pragma unroll
                for (int j = 0; j < 4; j++) FMA2(acc[i][j], a2[i], bp[j]);
        }
    }
    __syncthreads();

#pragma unroll
    for (int i = 0; i < 4; i++) {
        int node = min(n0 + row0 + i, NN - 1);
        const float* hold = g_h + (size_t)node * HID + col0;
        float* vrow = Hs + (row0 + i) * 132;
#pragma unroll
        for (int j = 0; j < 4; j++) {
            float lo, hi;
            UNPACK2(lo, hi, acc[i][j]);
            vrow[col0 + 2 * j]     = lo + b2v[2 * j]     + hold[2 * j];
            vrow[col0 + 2 * j + 1] = hi + b2v[2 * j + 1] + hold[2 * j + 1];
        }
    }
    __syncthreads();

    int lane = tid & 31, w = tid >> 5;
    for (int r = w; r < 64; r += 8) {
        int node = n0 + r;
        float4 v = *(float4*)(Hs + r * 132 + lane * 4);
        float s = v.x + v.y + v.z + v.w;
        float sq = fmaf(v.x, v.x, fmaf(v.y, v.y, fmaf(v.z, v.z, v.w * v.w)));
#pragma unroll
        for (int o = 16; o; o >>= 1) {
            s += __shfl_xor_sync(0xffffffffu, s, o);
            sq += __shfl_xor_sync(0xffffffffu, sq, o);
        }
        float mu = s * (1.f / HID);
        float var = sq * (1.f / HID) - mu * mu;
        float rstd = rsqrtf(var + 1e-5f);
        if (node < NN) {
            int cc = lane * 4;
            float4 o;
            o.x = (v.x - mu) * rstd * lng[cc + 0] + lnb[cc + 0];
            o.y = (v.y - mu) * rstd * lng[cc + 1] + lnb[cc + 1];
            o.z = (v.z - mu) * rstd * lng[cc + 2] + lnb[cc + 2];
            o.w = (v.w - mu) * rstd * lng[cc + 3] + lnb[cc + 3];
            *(float4*)(g_h + (size_t)node * HID + cc) = o;
        }
    }
}

// ---------------------------------------------------------------------------
// Head kernel (unchanged, known-good)
// ---------------------------------------------------------------------------
__global__ void __launch_bounds__(256)
head_kernel(const float* __restrict__ W, const float* __restrict__ b,
            float* __restrict__ out) {
    __shared__ __align__(16) float Ast[16 * 65];
    __shared__ __align__(16) float Bs[16 * 128];

    int tid = threadIdx.x;
    int tx = tid & 15, ty = tid >> 4;
    const int col0 = tx * 8, row0 = ty * 4;
    int n0 = blockIdx.x * 64;
    int le = tid >> 2;
    int kb = (tid & 3) * 4;
    int lnode = min(n0 + le, NN - 1);

    u64 acc[4][4];
#pragma unroll
    for (int i = 0; i < 4; i++)
#pragma unroll
        for (int j = 0; j < 4; j++) acc[i][j] = 0ull;

    float bv[8];
#pragma unroll
    for (int j = 0; j < 8; j++) bv[j] = b[col0 + j];

    for (int c = 0; c < 8; c++) {
        const float* ap = g_h + (size_t)lnode * HID + c * 16 + kb;
        float4 v = *(const float4*)ap;
        const float* wp = W + c * 16 * 128;
        float4 w0 = *(const float4*)(wp + tid * 8);
        float4 w1 = *(const float4*)(wp + tid * 8 + 4);
        __syncthreads();
        Ast[(kb + 0) * 65 + le] = v.x;
        Ast[(kb + 1) * 65 + le] = v.y;
        Ast[(kb + 2) * 65 + le] = v.z;
        Ast[(kb + 3) * 65 + le] = v.w;
        *(float4*)(Bs + tid * 8) = w0;
        *(float4*)(Bs + tid * 8 + 4) = w1;
        __syncthreads();
#pragma unroll
        for (int kk = 0; kk < 16; kk++) {
            u64 a2[4];
#pragma unroll
            for (int i = 0; i < 4; i++) {
                float a = Ast[kk * 65 + row0 + i];
                PACK2(a2[i], a, a);
            }
            ulonglong2 qq0 = *(const ulonglong2*)(Bs + kk * 128 + col0);
            ulonglong2 qq1 = *(const ulonglong2*)(Bs + kk * 128 + col0 + 4);
            u64 bp[4] = {qq0.x, qq0.y, qq1.x, qq1.y};
#pragma unroll
            for (int i = 0; i < 4; i++)
#pragma unroll
                for (int j = 0; j < 4; j++) FMA2(acc[i][j], a2[i], bp[j]);
        }
    }

#pragma unroll
    for (int i = 0; i < 4; i++) {
        int node = n0 + row0 + i;
        if (node < NN) {
            float f[8];
#pragma unroll
            for (int j = 0; j < 4; j++) UNPACK2(f[2 * j], f[2 * j + 1], acc[i][j]);
            float4 o0 = {f[0] + bv[0], f[1] + bv[1], f[2] + bv[2], f[3] + bv[3]};
            float4 o1 = {f[4] + bv[4], f[5] + bv[5], f[6] + bv[6], f[7] + bv[7]};
            *(float4*)(out + (size_t)node * HID + col0) = o0;
            *(float4*)(out + (size_t)node * HID + col0 + 4) = o1;
        }
    }
}

// ---------------------------------------------------------------------------
extern "C" void kernel_launch(void* const* d_in, const int* in_sizes, int n_in,
                              void* d_out, int out_size) {
    const float* x = (const float*)d_in[0];
    const void* ei = d_in[1];
    const float* ea = (const float*)d_in[2];
    const float* enc_W = (const float*)d_in[3];
    const float* enc_b = (const float*)d_in[4];
    const float* enc_g = (const float*)d_in[5];
    const float* enc_beta = (const float*)d_in[6];
    const float* msg_W1 = (const float*)d_in[7];
    const float* msg_b1 = (const float*)d_in[8];
    const float* msg_W2 = (const float*)d_in[9];
    const float* msg_b2 = (const float*)d_in[10];
    const float* upd_W1 = (const float*)d_in[11];
    const float* upd_b1 = (const float*)d_in[12];
    const float* upd_W2 = (const float*)d_in[13];
    const float* upd_b2 = (const float*)d_in[14];
    const float* ln_g = (const float*)d_in[15];
    const float* ln_beta = (const float*)d_in[16];
    const float* head_W = (const float*)d_in[17];
    const float* head_b = (const float*)d_in[18];
    float* out = (float*)d_out;

    static float* dP = nullptr;
    static float* dQ = nullptr;
    static unsigned *dW2h, *dW2l, *dW1h, *dW1l;
    static int attr_done = 0;
    if (!attr_done) {
        cudaGetSymbolAddress((void**)&dP, g_P);
        cudaGetSymbolAddress((void**)&dQ, g_Q);
        cudaGetSymbolAddress((void**)&dW2h, gW2h);
        cudaGetSymbolAddress((void**)&dW2l, gW2l);
        cudaGetSymbolAddress((void**)&dW1h, gW1h);
        cudaGetSymbolAddress((void**)&dW1l, gW1l);
        cudaFuncSetAttribute(msg_kernel, cudaFuncAttributeMaxDynamicSharedMemorySize, MSG_SMEM);
        attr_done = 1;
    }

    const int NB = (NN + 63) / 64;

    detect_ei_kernel<<<1, 32>>>((const unsigned*)ei);
    pack_ea_kernel<<<(EE * 4) / 256, 256>>>(ea);
    pack_w_kernel<<<72, 256>>>(msg_W1, msg_W2);
    enc_kernel<<<NN, 128>>>(x, enc_W, enc_b, enc_g, enc_beta);
    zero_deg_kernel<<<(NN + 255) / 256, 256>>>();
    deg_kernel<<<(EE + 255) / 256, 256>>>(ei);
    rdeg_kernel<<<(NN + 255) / 256, 256>>>();

    for (int l = 0; l < 2; l++) {
        const float* W1 = msg_W1 + (size_t)l * 272 * HID;
        nodemm_kernel<<<NB, 256>>>(W1, dP);
        nodemm_kernel<<<NB, 256>>>(W1 + (size_t)128 * HID, dQ);
        zero_aggr_kernel<<<((size_t)NN * HID + 255) / 256, 256>>>();
        msg_kernel<<<EE / 64, 256, MSG_SMEM>>>(
            ei,
            dW2h + l * 8192, dW2l + l * 8192,
            dW1h + l * 1024, dW1l + l * 1024,
            msg_b1 + l * HID, msg_b2 + l * HID);
        upd_kernel<<<NB, 256>>>(
            upd_W1 + (size_t)l * 256 * HID, upd_b1 + l * HID,
            upd_W2 + (size_t)l * HID * HID, upd_b2 + l * HID,
            ln_g + l * HID, ln_beta + l * HID);
    }

    head_kernel<<<NB, 256>>>(head_W, head_b, out);
}

// round 11
// speedup vs baseline: 1.5600x; 1.5600x over previous
#include <cuda_runtime.h>
#include <cuda_bf16.h>
#include <cstdint>

#define NN 50000
#define EE 800000
#define HID 128

// Scratch (device globals — no allocation allowed)
__device__ float g_h[(size_t)NN * HID];
__device__ float g_aggr[(size_t)NN * HID];
__device__ float g_P[(size_t)NN * HID];   // h @ W1a (tgt part)
__device__ float g_Q[(size_t)NN * HID];   // h @ W1b (src part)
__device__ float g_rdeg[NN];
__device__ int g_ei_is64;

typedef unsigned long long u64;

#define FMA2(d, a, b) asm("fma.rn.f32x2 %0, %1, %2, %0;" : "+l"(d) : "l"(a), "l"(b))
#define PACK2(d, lo, hi) asm("mov.b64 %0, {%1, %2};" : "=l"(d) : "f"(lo), "f"(hi))
#define UNPACK2(lo, hi, s) asm("mov.b64 {%0, %1}, %2;" : "=f"(lo), "=f"(hi) : "l"(s))

#define RED2(ptr, a, b) \
    asm volatile("red.global.add.v2.f32 [%0], {%1, %2};" \
                 :: "l"(ptr), "f"(a), "f"(b) : "memory")

#define MMA16816(cc, aa, bb) \
    asm volatile("mma.sync.aligned.m16n8k16.row.col.f32.bf16.bf16.f32 " \
                 "{%0,%1,%2,%3}, {%4,%5,%6,%7}, {%8,%9}, {%0,%1,%2,%3};" \
                 : "+f"(cc[0]), "+f"(cc[1]), "+f"(cc[2]), "+f"(cc[3]) \
                 : "r"(aa[0]), "r"(aa[1]), "r"(aa[2]), "r"(aa[3]), \
                   "r"(bb[0]), "r"(bb[1]))

// split float pair into bf16 hi-pack and bf16 residual-pack (x in low bits)
__device__ __forceinline__ void split2(float x, float y, unsigned& hi, unsigned& lo) {
    __nv_bfloat16 xh = __float2bfloat16_rn(x);
    __nv_bfloat16 yh = __float2bfloat16_rn(y);
    __nv_bfloat16 xl = __float2bfloat16_rn(x - __bfloat162float(xh));
    __nv_bfloat16 yl = __float2bfloat16_rn(y - __bfloat162float(yh));
    hi = ((unsigned)__bfloat16_as_ushort(yh) << 16) | __bfloat16_as_ushort(xh);
    lo = ((unsigned)__bfloat16_as_ushort(yl) << 16) | __bfloat16_as_ushort(xl);
}

// perm: k-pair p (0..7) -> u32 slot so that (tig, tig+4) are adjacent
__device__ __forceinline__ int permp(int p) { return 2 * (p & 3) + (p >> 2); }

__device__ __forceinline__ int load_ei(const void* ei, size_t idx, int is64) {
    int v = is64 ? (int)((const long long*)ei)[idx] : ((const int*)ei)[idx];
    return min(max(v, 0), NN - 1);
}

// ---------------------------------------------------------------------------
// init_aggr: zero g_aggr AND probe edge_index dtype (block 0, thread 0)
// ---------------------------------------------------------------------------
__global__ void init_aggr_kernel(const unsigned* __restrict__ raw) {
    size_t i = (size_t)blockIdx.x * blockDim.x + threadIdx.x;
    if (i < (size_t)NN * HID) g_aggr[i] = 0.f;
    if (blockIdx.x == 0 && threadIdx.x == 0) {
        int is64 = 1;
        for (int k = 0; k < 64; k++)
            if (raw[2 * k + 1] != 0u) { is64 = 0; break; }
        g_ei_is64 = is64;
    }
}

// ---------------------------------------------------------------------------
// Encoder
// ---------------------------------------------------------------------------
__global__ void enc_kernel(const float* __restrict__ x, const float* __restrict__ W,
                           const float* __restrict__ b, const float* __restrict__ g,
                           const float* __restrict__ beta) {
    int node = blockIdx.x;
    int t = threadIdx.x;
    __shared__ float sx[32];
    __shared__ float red[8];
    if (t < 32) sx[t] = x[node * 32 + t];
    __syncthreads();
    float acc = b[t];
#pragma unroll
    for (int k = 0; k < 32; k++) acc = fmaf(sx[k], W[k * HID + t], acc);
    acc = fmaxf(acc, 0.f);
    float s = acc, sq = acc * acc;
#pragma unroll
    for (int o = 16; o; o >>= 1) {
        s += __shfl_xor_sync(0xffffffffu, s, o);
        sq += __shfl_xor_sync(0xffffffffu, sq, o);
    }
    int w = t >> 5;
    if ((t & 31) == 0) { red[w] = s; red[4 + w] = sq; }
    __syncthreads();
    s = red[0] + red[1] + red[2] + red[3];
    sq = red[4] + red[5] + red[6] + red[7];
    float mu = s * (1.f / HID);
    float var = sq * (1.f / HID) - mu * mu;
    g_h[(size_t)node * HID + t] = (acc - mu) * rsqrtf(var + 1e-5f) * g[t] + beta[t];
}

// ---------------------------------------------------------------------------
// Degree helpers
// ---------------------------------------------------------------------------
__global__ void zero_deg_kernel() {
    int i = blockIdx.x * blockDim.x + threadIdx.x;
    if (i < NN) g_rdeg[i] = 0.f;
}
__global__ void deg_kernel(const void* __restrict__ ei) {
    int e = blockIdx.x * blockDim.x + threadIdx.x;
    int is64 = g_ei_is64;
    if (e < EE) atomicAdd(&g_rdeg[load_ei(ei, (size_t)EE + e, is64)], 1.f);
}
__global__ void rdeg_kernel() {
    int i = blockIdx.x * blockDim.x + threadIdx.x;
    if (i < NN) g_rdeg[i] = 1.f / fmaxf(g_rdeg[i], 1.f);
}

// ---------------------------------------------------------------------------
// Node GEMM (merged P/Q): blockIdx.y selects W half and output buffer
//   y=0: P = g_h @ W1[0:128]     y=1: Q = g_h @ W1[128:256]
// ---------------------------------------------------------------------------
__global__ void __launch_bounds__(256)
nodemm2_kernel(const float* __restrict__ W1, float* __restrict__ P, float* __restrict__ Q) {
    __shared__ __align__(16) float Ast[16 * 65];
    __shared__ __align__(16) float Bs[16 * 128];

    const float* W = W1 + (size_t)blockIdx.y * 128 * HID;
    float* out = blockIdx.y ? Q : P;

    int tid = threadIdx.x;
    int tx = tid & 15, ty = tid >> 4;
    const int col0 = tx * 8, row0 = ty * 4;
    int n0 = blockIdx.x * 64;
    int le = tid >> 2;
    int kb = (tid & 3) * 4;
    int lnode = min(n0 + le, NN - 1);

    u64 acc[4][4];
#pragma unroll
    for (int i = 0; i < 4; i++)
#pragma unroll
        for (int j = 0; j < 4; j++) acc[i][j] = 0ull;

    for (int c = 0; c < 8; c++) {
        const float* ap = g_h + (size_t)lnode * HID + c * 16 + kb;
        float4 v = *(const float4*)ap;
        const float* wp = W + c * 16 * 128;
        float4 w0 = *(const float4*)(wp + tid * 8);
        float4 w1 = *(const float4*)(wp + tid * 8 + 4);
        __syncthreads();
        Ast[(kb + 0) * 65 + le] = v.x;
        Ast[(kb + 1) * 65 + le] = v.y;
        Ast[(kb + 2) * 65 + le] = v.z;
        Ast[(kb + 3) * 65 + le] = v.w;
        *(float4*)(Bs + tid * 8) = w0;
        *(float4*)(Bs + tid * 8 + 4) = w1;
        __syncthreads();
#pragma unroll
        for (int kk = 0; kk < 16; kk++) {
            u64 a2[4];
#pragma unroll
            for (int i = 0; i < 4; i++) {
                float a = Ast[kk * 65 + row0 + i];
                PACK2(a2[i], a, a);
            }
            ulonglong2 qq0 = *(const ulonglong2*)(Bs + kk * 128 + col0);
            ulonglong2 qq1 = *(const ulonglong2*)(Bs + kk * 128 + col0 + 4);
            u64 bp[4] = {qq0.x, qq0.y, qq1.x, qq1.y};
#pragma unroll
            for (int i = 0; i < 4; i++)
#pragma unroll
                for (int j = 0; j < 4; j++) FMA2(acc[i][j], a2[i], bp[j]);
        }
    }

#pragma unroll
    for (int i = 0; i < 4; i++) {
        int node = n0 + row0 + i;
        if (node < NN) {
            float f[8];
#pragma unroll
            for (int j = 0; j < 4; j++) UNPACK2(f[2 * j], f[2 * j + 1], acc[i][j]);
            float4 o0 = {f[0], f[1], f[2], f[3]};
            float4 o1 = {f[4], f[5], f[6], f[7]};
            *(float4*)(out + (size_t)node * HID + col0) = o0;
            *(float4*)(out + (size_t)node * HID + col0 + 4) = o1;
        }
    }
}

// ---------------------------------------------------------------------------
// Message kernel (R9-identical, validated 1994us):
//   pre = P[tgt] + Q[src] + ea @ W1c + b1     (GEMM1 K=16)
//   hidden = ReLU(pre)
//   m = hidden @ W2 + b2                      (K=128)
//   red.v2(g_aggr[tgt], m)
// ---------------------------------------------------------------------------
__global__ void __launch_bounds__(256)
msg_kernel(const void* __restrict__ ei, const float* __restrict__ ea,
           const float* __restrict__ W1c, const float* __restrict__ b1,
           const float* __restrict__ W2, const float* __restrict__ b2) {
    __shared__ __align__(16) unsigned sB_hi[128 * 10];
    __shared__ __align__(16) unsigned sB_lo[128 * 10];
    __shared__ __align__(16) unsigned sH_hi[64 * 70];
    __shared__ __align__(16) unsigned sH_lo[64 * 70];
    __shared__ int s_src[64];
    __shared__ int s_tgt[64];

    int tid = threadIdx.x;
    int lane = tid & 31, wid = tid >> 5;
    int gid = lane >> 2, tig = lane & 3;
    int wm = wid & 3, wn = wid >> 2;
    int e0 = blockIdx.x * 64;

    int le = tid >> 2;       // edge row 0..63
    int kq = tid & 3;        // float-quad within 16-k panel
    int bn = tid & 127;      // output column
    int bkh = tid >> 7;      // k-half (0/1)

    int is64 = g_ei_is64;
    if (tid < 64) s_src[tid] = load_ei(ei, (size_t)e0 + tid, is64);
    else if (tid < 128) s_tgt[tid - 64] = load_ei(ei, (size_t)EE + e0 + (tid - 64), is64);

    float acc[8][4];
#pragma unroll
    for (int t = 0; t < 8; t++)
#pragma unroll
        for (int j = 0; j < 4; j++) acc[t][j] = 0.f;

    unsigned* sA_hi = sH_hi;  // alias: [64][10]
    unsigned* sA_lo = sH_lo;

    const int q0 = permp(2 * kq), q1 = permp(2 * kq + 1);
    const int arow0 = (wm * 16 + gid) * 10 + 2 * tig;

    __syncthreads();

    // ================= GEMM1: single K=16 panel (ea @ W1c) =================
    {
        const float* ap = ea + (size_t)(e0 + le) * 16 + kq * 4;
        float4 v = *(const float4*)ap;
        float w[8];
        const float* wp = W1c + (size_t)(bkh * 8) * HID + bn;
#pragma unroll
        for (int kk = 0; kk < 8; kk++) w[kk] = wp[(size_t)kk * HID];

        unsigned h0, l0, h1, l1;
        split2(v.x, v.y, h0, l0);
        split2(v.z, v.w, h1, l1);
        sA_hi[le * 10 + q0] = h0; sA_lo[le * 10 + q0] = l0;
        sA_hi[le * 10 + q1] = h1; sA_lo[le * 10 + q1] = l1;
#pragma unroll
        for (int j = 0; j < 4; j++) {
            unsigned hi, lo;
            split2(w[2 * j], w[2 * j + 1], hi, lo);
            int q = permp(bkh * 4 + j);
            sB_hi[bn * 10 + q] = hi;
            sB_lo[bn * 10 + q] = lo;
        }
        __syncthreads();

        uint2 AH0 = *(uint2*)&sA_hi[arow0];
        uint2 AH1 = *(uint2*)&sA_hi[arow0 + 80];
        uint2 AL0 = *(uint2*)&sA_lo[arow0];
        uint2 AL1 = *(uint2*)&sA_lo[arow0 + 80];
        unsigned ah[4] = {AH0.x, AH1.x, AH0.y, AH1.y};
        unsigned al[4] = {AL0.x, AL1.x, AL0.y, AL1.y};
#pragma unroll
        for (int t = 0; t < 8; t++) {
            int br = (wn * 64 + t * 8 + gid) * 10 + 2 * tig;
            uint2 BH = *(uint2*)&sB_hi[br];
            uint2 BL = *(uint2*)&sB_lo[br];
            unsigned bh[2] = {BH.x, BH.y};
            unsigned bl[2] = {BL.x, BL.y};
            MMA16816(acc[t], ah, bh);
            MMA16816(acc[t], ah, bl);
            MMA16816(acc[t], al, bh);
        }
    }

    __syncthreads();  // GEMM1 mma reads done before sH overwrite

    // ---- += P[tgt] + Q[src] + b1, ReLU -> sH (packed for GEMM2 A-frags) ----
    {
        int r0 = wm * 16 + gid;
        int n0t = s_tgt[r0], n0s = s_src[r0];
        int n1t = s_tgt[r0 + 8], n1s = s_src[r0 + 8];
        const float* P0 = g_P + (size_t)n0t * HID;
        const float* Q0 = g_Q + (size_t)n0s * HID;
        const float* P1 = g_P + (size_t)n1t * HID;
        const float* Q1 = g_Q + (size_t)n1s * HID;
#pragma unroll
        for (int t = 0; t < 8; t++) {
            int col = wn * 64 + t * 8 + tig * 2;
            float bb0 = b1[col], bb1 = b1[col + 1];
            float2 p0 = *(const float2*)(P0 + col);
            float2 qq0 = *(const float2*)(Q0 + col);
            float2 p1 = *(const float2*)(P1 + col);
            float2 qq1 = *(const float2*)(Q1 + col);
            float x0 = fmaxf(acc[t][0] + bb0 + p0.x + qq0.x, 0.f);
            float x1 = fmaxf(acc[t][1] + bb1 + p0.y + qq0.y, 0.f);
            float x2 = fmaxf(acc[t][2] + bb0 + p1.x + qq1.x, 0.f);
            float x3 = fmaxf(acc[t][3] + bb1 + p1.y + qq1.y, 0.f);
            int c2 = col >> 4;
            int q = permp((t & 1) * 4 + tig);
            unsigned hi0, lo0, hi1, lo1;
            split2(x0, x1, hi0, lo0);
            split2(x2, x3, hi1, lo1);
            sH_hi[r0 * 70 + c2 * 8 + q] = hi0;
            sH_lo[r0 * 70 + c2 * 8 + q] = lo0;
            sH_hi[(r0 + 8) * 70 + c2 * 8 + q] = hi1;
            sH_lo[(r0 + 8) * 70 + c2 * 8 + q] = lo1;
#pragma unroll
            for (int j = 0; j < 4; j++) acc[t][j] = 0.f;
        }
    }
    __syncthreads();

    // ================= GEMM2: K=128, 8 panels =================
    for (int c = 0; c < 8; c++) {
        float w[8];
        const float* wp = W2 + (size_t)(c * 16 + bkh * 8) * HID + bn;
#pragma unroll
        for (int kk = 0; kk < 8; kk++) w[kk] = wp[(size_t)kk * HID];
        __syncthreads();
#pragma unroll
        for (int j = 0; j < 4; j++) {
            unsigned hi, lo;
            split2(w[2 * j], w[2 * j + 1], hi, lo);
            int q = permp(bkh * 4 + j);
            sB_hi[bn * 10 + q] = hi;
            sB_lo[bn * 10 + q] = lo;
        }
        __syncthreads();

        int ar = (wm * 16 + gid) * 70 + c * 8 + 2 * tig;
        uint2 AH0 = *(uint2*)&sH_hi[ar];
        uint2 AH1 = *(uint2*)&sH_hi[ar + 560];
        uint2 AL0 = *(uint2*)&sH_lo[ar];
        uint2 AL1 = *(uint2*)&sH_lo[ar + 560];
        unsigned ah[4] = {AH0.x, AH1.x, AH0.y, AH1.y};
        unsigned al[4] = {AL0.x, AL1.x, AL0.y, AL1.y};
#pragma unroll
        for (int t = 0; t < 8; t++) {
            int br = (wn * 64 + t * 8 + gid) * 10 + 2 * tig;
            uint2 BH = *(uint2*)&sB_hi[br];
            uint2 BL = *(uint2*)&sB_lo[br];
            unsigned bh[2] = {BH.x, BH.y};
            unsigned bl[2] = {BL.x, BL.y};
            MMA16816(acc[t], ah, bh);
            MMA16816(acc[t], ah, bl);
            MMA16816(acc[t], al, bh);
        }
    }

    // ---- scatter: m + b2 -> g_aggr[tgt] ----
    {
        int r0 = wm * 16 + gid;
        int n0 = s_tgt[r0], n1 = s_tgt[r0 + 8];
#pragma unroll
        for (int t = 0; t < 8; t++) {
            int col = wn * 64 + t * 8 + tig * 2;
            float bb0 = b2[col], bb1 = b2[col + 1];
            RED2(g_aggr + (size_t)n0 * HID + col, acc[t][0] + bb0, acc[t][1] + bb1);
            RED2(g_aggr + (size_t)n1 * HID + col, acc[t][2] + bb0, acc[t][3] + bb1);
        }
    }
}

// ---------------------------------------------------------------------------
// Update kernel (unchanged, known-good)
// ---------------------------------------------------------------------------
__global__ void __launch_bounds__(256)
upd_kernel(const float* __restrict__ W1, const float* __restrict__ b1,
           const float* __restrict__ W2, const float* __restrict__ b2,
           const float* __restrict__ lng, const float* __restrict__ lnb) {
    __shared__ __align__(16) float Ast[16 * 65];
    __shared__ __align__(16) float Bs[16 * 128];
    __shared__ __align__(16) float Hs[64 * 132];

    int tid = threadIdx.x;
    int tx = tid & 15, ty = tid >> 4;
    const int col0 = tx * 8, row0 = ty * 4;
    int n0 = blockIdx.x * 64;
    int le = tid >> 2;
    int kb = (tid & 3) * 4;
    int lnode = min(n0 + le, NN - 1);
    float rd = g_rdeg[lnode];

    u64 acc[4][4];
#pragma unroll
    for (int i = 0; i < 4; i++)
#pragma unroll
        for (int j = 0; j < 4; j++) acc[i][j] = 0ull;

    float b1v[8], b2v[8];
#pragma unroll
    for (int j = 0; j < 8; j++) { b1v[j] = b1[col0 + j]; b2v[j] = b2[col0 + j]; }

    for (int c = 0; c < 16; c++) {
        const float* ap = (c < 8) ? g_h + (size_t)lnode * HID + c * 16 + kb
                                  : g_aggr + (size_t)lnode * HID + (c - 8) * 16 + kb;
        float4 v = *(const float4*)ap;
        if (c >= 8) { v.x *= rd; v.y *= rd; v.z *= rd; v.w *= rd; }
        const float* wp = W1 + c * 16 * 128;
        float4 w0 = *(const float4*)(wp + tid * 8);
        float4 w1 = *(const float4*)(wp + tid * 8 + 4);
        __syncthreads();
        Ast[(kb + 0) * 65 + le] = v.x;
        Ast[(kb + 1) * 65 + le] = v.y;
        Ast[(kb + 2) * 65 + le] = v.z;
        Ast[(kb + 3) * 65 + le] = v.w;
        *(float4*)(Bs + tid * 8) = w0;
        *(float4*)(Bs + tid * 8 + 4) = w1;
        __syncthreads();
#pragma unroll
        for (int kk = 0; kk < 16; kk++) {
            u64 a2[4];
#pragma unroll
            for (int i = 0; i < 4; i++) {
                float a = Ast[kk * 65 + row0 + i];
                PACK2(a2[i], a, a);
            }
            ulonglong2 qq0 = *(const ulonglong2*)(Bs + kk * 128 + col0);
            ulonglong2 qq1 = *(const ulonglong2*)(Bs + kk * 128 + col0 + 4);
            u64 bp[4] = {qq0.x, qq0.y, qq1.x, qq1.y};
#pragma unroll
            for (int i = 0; i < 4; i++)
#pragma unroll
                for (int j = 0; j < 4; j++) FMA2(acc[i][j], a2[i], bp[j]);
        }
    }

#pragma unroll
    for (int i = 0; i < 4; i++) {
        float* hrow = Hs + (row0 + i) * 132;
#pragma unroll
        for (int j = 0; j < 4; j++) {
            float lo, hi;
            UNPACK2(lo, hi, acc[i][j]);
            hrow[col0 + 2 * j]     = fmaxf(lo + b1v[2 * j], 0.f);
            hrow[col0 + 2 * j + 1] = fmaxf(hi + b1v[2 * j + 1], 0.f);
            acc[i][j] = 0ull;
        }
    }
    __syncthreads();

    for (int c = 0; c < 8; c++) {
        const float* wp = W2 + c * 16 * 128;
        float4 w0 = *(const float4*)(wp + tid * 8);
        float4 w1 = *(const float4*)(wp + tid * 8 + 4);
        __syncthreads();
        *(float4*)(Bs + tid * 8) = w0;
        *(float4*)(Bs + tid * 8 + 4) = w1;
        __syncthreads();
#pragma unroll
        for (int kk = 0; kk < 16; kk++) {
            int k = c * 16 + kk;
            u64 a2[4];
#pragma unroll
            for (int i = 0; i < 4; i++) {
                float a = Hs[(row0 + i) * 132 + k];
                PACK2(a2[i], a, a);
            }
            ulonglong2 qq0 = *(const ulonglong2*)(Bs + kk * 128 + col0);
            ulonglong2 qq1 = *(const ulonglong2*)(Bs + kk * 128 + col0 + 4);
            u64 bp[4] = {qq0.x, qq0.y, qq1.x, qq1.y};
#pragma unroll
            for (int i = 0; i < 4; i++)
#pragma unroll
                for (int j = 0; j < 4; j++) FMA2(acc[i][j], a2[i], bp[j]);
        }
    }
    __syncthreads();

#pragma unroll
    for (int i = 0; i < 4; i++) {
        int node = min(n0 + row0 + i, NN - 1);
        const float* hold = g_h + (size_t)node * HID + col0;
        float* vrow = Hs + (row0 + i) * 132;
#pragma unroll
        for (int j = 0; j < 4; j++) {
            float lo, hi;
            UNPACK2(lo, hi, acc[i][j]);
            vrow[col0 + 2 * j]     = lo + b2v[2 * j]     + hold[2 * j];
            vrow[col0 + 2 * j + 1] = hi + b2v[2 * j + 1] + hold[2 * j + 1];
        }
    }
    __syncthreads();

    int lane = tid & 31, w = tid >> 5;
    for (int r = w; r < 64; r += 8) {
        int node = n0 + r;
        float4 v = *(float4*)(Hs + r * 132 + lane * 4);
        float s = v.x + v.y + v.z + v.w;
        float sq = fmaf(v.x, v.x, fmaf(v.y, v.y, fmaf(v.z, v.z, v.w * v.w)));
#pragma unroll
        for (int o = 16; o; o >>= 1) {
            s += __shfl_xor_sync(0xffffffffu, s, o);
            sq += __shfl_xor_sync(0xffffffffu, sq, o);
        }
        float mu = s * (1.f / HID);
        float var = sq * (1.f / HID) - mu * mu;
        float rstd = rsqrtf(var + 1e-5f);
        if (node < NN) {
            int cc = lane * 4;
            float4 o;
            o.x = (v.x - mu) * rstd * lng[cc + 0] + lnb[cc + 0];
            o.y = (v.y - mu) * rstd * lng[cc + 1] + lnb[cc + 1];
            o.z = (v.z - mu) * rstd * lng[cc + 2] + lnb[cc + 2];
            o.w = (v.w - mu) * rstd * lng[cc + 3] + lnb[cc + 3];
            *(float4*)(g_h + (size_t)node * HID + cc) = o;
        }
    }
}

// ---------------------------------------------------------------------------
// Head kernel (unchanged, known-good)
// ---------------------------------------------------------------------------
__global__ void __launch_bounds__(256)
head_kernel(const float* __restrict__ W, const float* __restrict__ b,
            float* __restrict__ out) {
    __shared__ __align__(16) float Ast[16 * 65];
    __shared__ __align__(16) float Bs[16 * 128];

    int tid = threadIdx.x;
    int tx = tid & 15, ty = tid >> 4;
    const int col0 = tx * 8, row0 = ty * 4;
    int n0 = blockIdx.x * 64;
    int le = tid >> 2;
    int kb = (tid & 3) * 4;
    int lnode = min(n0 + le, NN - 1);

    u64 acc[4][4];
#pragma unroll
    for (int i = 0; i < 4; i++)
#pragma unroll
        for (int j = 0; j < 4; j++) acc[i][j] = 0ull;

    float bv[8];
#pragma unroll
    for (int j = 0; j < 8; j++) bv[j] = b[col0 + j];

    for (int c = 0; c < 8; c++) {
        const float* ap = g_h + (size_t)lnode * HID + c * 16 + kb;
        float4 v = *(const float4*)ap;
        const float* wp = W + c * 16 * 128;
        float4 w0 = *(const float4*)(wp + tid * 8);
        float4 w1 = *(const float4*)(wp + tid * 8 + 4);
        __syncthreads();
        Ast[(kb + 0) * 65 + le] = v.x;
        Ast[(kb + 1) * 65 + le] = v.y;
        Ast[(kb + 2) * 65 + le] = v.z;
        Ast[(kb + 3) * 65 + le] = v.w;
        *(float4*)(Bs + tid * 8) = w0;
        *(float4*)(Bs + tid * 8 + 4) = w1;
        __syncthreads();
#pragma unroll
        for (int kk = 0; kk < 16; kk++) {
            u64 a2[4];
#pragma unroll
            for (int i = 0; i < 4; i++) {
                float a = Ast[kk * 65 + row0 + i];
                PACK2(a2[i], a, a);
            }
            ulonglong2 qq0 = *(const ulonglong2*)(Bs + kk * 128 + col0);
            ulonglong2 qq1 = *(const ulonglong2*)(Bs + kk * 128 + col0 + 4);
            u64 bp[4] = {qq0.x, qq0.y, qq1.x, qq1.y};
#pragma unroll
            for (int i = 0; i < 4; i++)
#pragma unroll
                for (int j = 0; j < 4; j++) FMA2(acc[i][j], a2[i], bp[j]);
        }
    }

#pragma unroll
    for (int i = 0; i < 4; i++) {
        int node = n0 + row0 + i;
        if (node < NN) {
            float f[8];
#pragma unroll
            for (int j = 0; j < 4; j++) UNPACK2(f[2 * j], f[2 * j + 1], acc[i][j]);
            float4 o0 = {f[0] + bv[0], f[1] + bv[1], f[2] + bv[2], f[3] + bv[3]};
            float4 o1 = {f[4] + bv[4], f[5] + bv[5], f[6] + bv[6], f[7] + bv[7]};
            *(float4*)(out + (size_t)node * HID + col0) = o0;
            *(float4*)(out + (size_t)node * HID + col0 + 4) = o1;
        }
    }
}

// ---------------------------------------------------------------------------
extern "C" void kernel_launch(void* const* d_in, const int* in_sizes, int n_in,
                              void* d_out, int out_size) {
    const float* x = (const float*)d_in[0];
    const void* ei = d_in[1];
    const float* ea = (const float*)d_in[2];
    const float* enc_W = (const float*)d_in[3];
    const float* enc_b = (const float*)d_in[4];
    const float* enc_g = (const float*)d_in[5];
    const float* enc_beta = (const float*)d_in[6];
    const float* msg_W1 = (const float*)d_in[7];
    const float* msg_b1 = (const float*)d_in[8];
    const float* msg_W2 = (const float*)d_in[9];
    const float* msg_b2 = (const float*)d_in[10];
    const float* upd_W1 = (const float*)d_in[11];
    const float* upd_b1 = (const float*)d_in[12];
    const float* upd_W2 = (const float*)d_in[13];
    const float* upd_b2 = (const float*)d_in[14];
    const float* ln_g = (const float*)d_in[15];
    const float* ln_beta = (const float*)d_in[16];
    const float* head_W = (const float*)d_in[17];
    const float* head_b = (const float*)d_in[18];
    float* out = (float*)d_out;

    static float* dP = nullptr;
    static float* dQ = nullptr;
    if (!dP) {
        cudaGetSymbolAddress((void**)&dP, g_P);
        cudaGetSymbolAddress((void**)&dQ, g_Q);
    }

    const int NB = (NN + 63) / 64;
    const int ZB = ((size_t)NN * HID + 255) / 256;

    // ---- layer 0; msg at launch index 3 so ncu profiles it ----
    init_aggr_kernel<<<ZB, 256>>>((const unsigned*)ei);             // 0: zero aggr + dtype probe
    enc_kernel<<<NN, 128>>>(x, enc_W, enc_b, enc_g, enc_beta);      // 1
    nodemm2_kernel<<<dim3(NB, 2), 256>>>(msg_W1, dP, dQ);           // 2: P and Q
    msg_kernel<<<EE / 64, 256>>>(                                   // 3 <- profiled
        ei, ea,
        msg_W1 + (size_t)256 * HID, msg_b1,
        msg_W2, msg_b2);
    zero_deg_kernel<<<(NN + 255) / 256, 256>>>();                   // 4
    deg_kernel<<<(EE + 255) / 256, 256>>>(ei);                      // 5
    rdeg_kernel<<<(NN + 255) / 256, 256>>>();                       // 6
    upd_kernel<<<NB, 256>>>(                                        // 7
        upd_W1, upd_b1, upd_W2, upd_b2, ln_g, ln_beta);

    // ---- layer 1 ----
    const float* W1_1 = msg_W1 + (size_t)272 * HID;
    nodemm2_kernel<<<dim3(NB, 2), 256>>>(W1_1, dP, dQ);             // 8
    init_aggr_kernel<<<ZB, 256>>>((const unsigned*)ei);             // 9
    msg_kernel<<<EE / 64, 256>>>(                                   // 10
        ei, ea,
        W1_1 + (size_t)256 * HID, msg_b1 + HID,
        msg_W2 + (size_t)HID * HID, msg_b2 + HID);
    upd_kernel<<<NB, 256>>>(                                        // 11
        upd_W1 + (size_t)256 * HID, upd_b1 + HID,
        upd_W2 + (size_t)HID * HID, upd_b2 + HID,
        ln_g + HID, ln_beta + HID);

    head_kernel<<<NB, 256>>>(head_W, head_b, out);                  // 12
}